// round 9
// baseline (speedup 1.0000x reference)
#include <cuda_runtime.h>
#include <cuda.h>
#include <cuda_bf16.h>
#include <math.h>
#include <cstdint>

// ---------------------------------------------------------------------------
// Problem constants
// ---------------------------------------------------------------------------
#define NROWS 8192       // 4B rows in rep
#define HALF  4096       // rows per input
#define D     512        // embedding dim

// GEMM config: 128x128 CTA tile, 8 warps of 64x32, K chunked by 64 bf16
#define TILE    128
#define KC      64
#define NCHUNK  (D / KC)           // 8
#define NT      256
#define NSTAGE  6
#define OP_B    (TILE * KC * 2)    // 16384 B per operand per stage
#define SLOT_B  (2 * OP_B)         // A + B per stage = 32 KB
#define SMEM_DYN (2048 + NSTAGE * SLOT_B)  // align+hdr + 6 stages = 198656 B

#define NTILES  2080               // 64*65/2 upper-triangular 128x128 tiles

// ---------------------------------------------------------------------------
// Static scratch
// ---------------------------------------------------------------------------
__device__ __align__(16) __nv_bfloat16 g_repb[(size_t)NROWS * D];  // 8 MB
__device__ double g_acc[2];        // [0] = S_offdiag (x2), [1] = nominator
__device__ unsigned int g_done;    // CTA arrival counter (self-resetting)

// ---------------------------------------------------------------------------
// Helpers
// ---------------------------------------------------------------------------
__device__ __forceinline__ uint32_t smem_u32(const void* p) {
    uint32_t a;
    asm("{ .reg .u64 t; cvta.to.shared.u64 t, %1; cvt.u32.u64 %0, t; }"
        : "=r"(a) : "l"(p));
    return a;
}

#define MBAR_INIT(addr, cnt) \
    asm volatile("mbarrier.init.shared.b64 [%0], %1;" :: "r"(addr), "r"(cnt) : "memory")

#define MBAR_ARRIVE(addr) \
    asm volatile("mbarrier.arrive.shared.b64 _, [%0];" :: "r"(addr) : "memory")

#define MBAR_WAIT(addr, par) do {                                              \
    uint32_t _m = (addr), _p = (par), _d;                                      \
    asm volatile("{\n\t.reg .pred p;\n\t"                                      \
        "mbarrier.try_wait.parity.acquire.cta.shared::cta.b64 p, [%1], %2;\n\t"\
        "selp.b32 %0, 1, 0, p;\n\t}"                                           \
        : "=r"(_d) : "r"(_m), "r"(_p) : "memory");                             \
    if (!_d) {                                                                 \
        asm volatile("{\n\t.reg .pred P1;\n\t"                                 \
            "W%=:\n\t"                                                         \
            "mbarrier.try_wait.parity.acquire.cta.shared::cta.b64 P1, [%0], %1, 0x989680;\n\t" \
            "@P1 bra.uni DN%=;\n\tbra.uni W%=;\n\tDN%=:\n\t}"                  \
            :: "r"(_m), "r"(_p) : "memory");                                   \
    }                                                                          \
} while (0)

// TMA: arm barrier for 32KB and issue A+B box loads (64 x 128 bf16, SW128)
__device__ __forceinline__ void tma_issue(uint32_t bar, uint32_t dstA, uint32_t dstB,
                                          const CUtensorMap* tm,
                                          int kx, int rowA, int rowB) {
    asm volatile("mbarrier.arrive.expect_tx.shared.b64 _, [%0], %1;"
                 :: "r"(bar), "r"(32768u) : "memory");
    asm volatile("cp.async.bulk.tensor.2d.shared::cta.global.tile.mbarrier::complete_tx::bytes "
                 "[%0], [%1, {%2, %3}], [%4];"
                 :: "r"(dstA), "l"(tm), "r"(kx), "r"(rowA), "r"(bar) : "memory");
    asm volatile("cp.async.bulk.tensor.2d.shared::cta.global.tile.mbarrier::complete_tx::bytes "
                 "[%0], [%1, {%2, %3}], [%4];"
                 :: "r"(dstB), "l"(tm), "r"(kx), "r"(rowB), "r"(bar) : "memory");
}

__device__ __forceinline__ void ldmx4(uint32_t& r0, uint32_t& r1,
                                      uint32_t& r2, uint32_t& r3, uint32_t a) {
    asm volatile("ldmatrix.sync.aligned.m8n8.x4.shared.b16 {%0,%1,%2,%3}, [%4];"
                 : "=r"(r0), "=r"(r1), "=r"(r2), "=r"(r3) : "r"(a));
}

__device__ __forceinline__ void mma16816(float* c, const uint32_t* a,
                                         const uint32_t* b) {
    asm volatile(
        "mma.sync.aligned.m16n8k16.row.col.f32.bf16.bf16.f32 "
        "{%0,%1,%2,%3}, {%4,%5,%6,%7}, {%8,%9}, {%0,%1,%2,%3};"
        : "+f"(c[0]), "+f"(c[1]), "+f"(c[2]), "+f"(c[3])
        : "r"(a[0]), "r"(a[1]), "r"(a[2]), "r"(a[3]), "r"(b[0]), "r"(b[1]));
}

// FMA-only exp(2*x) via 2^(x*2*log2e). Avoids MUFU. Rel err <= ~4e-6.
__device__ __forceinline__ float fast_exp2dot(float x) {
    float t  = x * 2.88539008177792681f;   // 2*log2(e)
    float fn = t + 12582912.0f;
    int   m  = __float_as_int(fn) - 0x4B400000;
    float r  = t - (fn - 12582912.0f);
    float p  = 1.3333558146e-3f;
    p = fmaf(p, r, 9.6181291e-3f);
    p = fmaf(p, r, 5.5504108664e-2f);
    p = fmaf(p, r, 2.4022650696e-1f);
    p = fmaf(p, r, 6.9314718056e-1f);
    p = fmaf(p, r, 1.0f);
    return __int_as_float(__float_as_int(p) + (m << 23));
}

// ---------------------------------------------------------------------------
// K1: L2-normalize rows of [emb_i; emb_j] -> bf16 g_repb. One block per row.
// Block 0 also zeroes the accumulators.
// ---------------------------------------------------------------------------
__global__ void normalize_kernel(const float* __restrict__ a,
                                 const float* __restrict__ b) {
    int row = blockIdx.x;
    int tid = threadIdx.x;  // 128
    if (row == 0 && tid == 0) { g_acc[0] = 0.0; g_acc[1] = 0.0; }

    const float* src = (row < HALF) ? (a + (size_t)row * D)
                                    : (b + (size_t)(row - HALF) * D);

    float4 v = reinterpret_cast<const float4*>(src)[tid];
    float ss = v.x * v.x + v.y * v.y + v.z * v.z + v.w * v.w;

    #pragma unroll
    for (int o = 16; o > 0; o >>= 1)
        ss += __shfl_xor_sync(0xFFFFFFFFu, ss, o);

    __shared__ float ws[4];
    int wid = tid >> 5, lane = tid & 31;
    if (lane == 0) ws[wid] = ss;
    __syncthreads();

    float total = ws[0] + ws[1] + ws[2] + ws[3];
    float inv = rsqrtf(fmaxf(total, 1e-24f));  // == x / max(norm, 1e-12)

    __nv_bfloat162 lo = __floats2bfloat162_rn(v.x * inv, v.y * inv);
    __nv_bfloat162 hi = __floats2bfloat162_rn(v.z * inv, v.w * inv);
    uint2 pk;
    pk.x = *reinterpret_cast<uint32_t*>(&lo);
    pk.y = *reinterpret_cast<uint32_t*>(&hi);
    reinterpret_cast<uint2*>(g_repb + (size_t)row * D)[tid] = pk;
}

// ---------------------------------------------------------------------------
// K2: bf16 mma.sync GEMM, warp-autonomous 6-stage TMA pipeline with
// double-buffered fragments (no __syncthreads in the mainloop).
// ---------------------------------------------------------------------------
__global__ __launch_bounds__(NT, 1)
void gemm_exp_kernel(float* __restrict__ out,
                     const __grid_constant__ CUtensorMap tmap) {
    // Decode linear tile index -> (bi, bj), bj >= bi.
    int idx = blockIdx.x;
    int bi  = (int)((129.0f - sqrtf(16641.0f - 8.0f * (float)idx)) * 0.5f);
    if (bi > 63) bi = 63;
    while (bi * (129 - bi) / 2 > idx) bi--;
    while ((bi + 1) * (129 - (bi + 1)) / 2 <= idx) bi++;
    int bj = bi + (idx - bi * (129 - bi) / 2);

    extern __shared__ char smraw[];
    uint32_t raw  = smem_u32(smraw);
    uint32_t base = (raw + 1023u) & ~1023u;   // 1024-align (SW128 atom span)
    uint32_t stg  = base + 1024;              // stages start here
    // header: full[s] at base+8*s (s<6); empty0 base+64; empty1 base+72;
    //         wred at base+128 (64B)

    const int tid    = threadIdx.x;
    const int wid    = tid >> 5;
    const int lane   = tid & 31;
    const int warp_m = wid & 1;      // 2 warps down M (64 rows each)
    const int warp_n = wid >> 1;     // 4 warps across N (32 cols each)

    const int rowA = bi * TILE;
    const int rowB = bj * TILE;

    if (tid == 0) {
        #pragma unroll
        for (int s = 0; s < NSTAGE; s++) MBAR_INIT(base + 8 * s, 1);
        MBAR_INIT(base + 64, 8);   // empty0 (slot 0 recycle), 8 warp arrives
        MBAR_INIT(base + 72, 8);   // empty1 (slot 1 recycle)
    }
    __syncthreads();

    // Prologue: arm chunks 0..5 into slots 0..5
    if (tid == 0) {
        #pragma unroll
        for (int s = 0; s < NSTAGE; s++) {
            uint32_t sl = stg + (uint32_t)s * SLOT_B;
            tma_issue(base + 8 * s, sl, sl + OP_B, &tmap, s * KC, rowA, rowB);
        }
    }

    float acc[4][4][4];   // [mf][nf][frag]
    #pragma unroll
    for (int mf = 0; mf < 4; mf++)
        #pragma unroll
        for (int nf = 0; nf < 4; nf++)
            #pragma unroll
            for (int e = 0; e < 4; e++)
                acc[mf][nf][e] = 0.0f;

    // Per-lane ldmatrix address components (SW128 swizzle-aware)
    const int a_row = lane & 15;
    const int a_hi  = lane >> 4;
    const int a_sw  = a_row & 7;
    const int b_n   = ((lane >> 4) << 3) + (lane & 7);
    const int b_hi  = (lane >> 3) & 1;
    const int b_sw  = b_n & 7;

    uint32_t afr[2][4][4];   // double-buffered fragments
    uint32_t bfr[2][4][2];

    // Fragment loader for (slot base sA, k-step ks) into buffer bx
    #define LOADF(bx, sAq, ksq) do {                                           \
        uint32_t _sA = (sAq);                                                  \
        uint32_t _sB = _sA + OP_B;                                             \
        _Pragma("unroll")                                                      \
        for (int mf = 0; mf < 4; mf++) {                                       \
            int grow = warp_m * 64 + mf * 16 + a_row;                          \
            uint32_t ca = (uint32_t)((2 * (ksq) + a_hi) ^ a_sw);               \
            ldmx4(afr[bx][mf][0], afr[bx][mf][1],                              \
                  afr[bx][mf][2], afr[bx][mf][3],                              \
                  _sA + grow * 128 + ca * 16);                                 \
        }                                                                      \
        _Pragma("unroll")                                                      \
        for (int np = 0; np < 2; np++) {                                       \
            int gn = warp_n * 32 + np * 16 + b_n;                              \
            uint32_t cb = (uint32_t)((2 * (ksq) + b_hi) ^ b_sw);               \
            uint32_t r0, r1, r2, r3;                                           \
            ldmx4(r0, r1, r2, r3, _sB + gn * 128 + cb * 16);                   \
            bfr[bx][2 * np][0] = r0;     bfr[bx][2 * np][1] = r1;              \
            bfr[bx][2 * np + 1][0] = r2; bfr[bx][2 * np + 1][1] = r3;          \
        }                                                                      \
    } while (0)

    // Warp-local prologue: wait chunk 0, load its first k-step fragments
    MBAR_WAIT(base + 0, 0);
    LOADF(0, stg, 0);

    #pragma unroll 1
    for (int j = 0; j < NCHUNK; j++) {
        uint32_t sA = stg + (uint32_t)(j % NSTAGE) * SLOT_B;

        #pragma unroll
        for (int ks = 0; ks < 4; ks++) {
            const int buf = ks & 1;
            const int nb  = buf ^ 1;

            // Prefetch next k-step's fragments before this step's MMAs
            if (ks < 3) {
                LOADF(nb, sA, ks + 1);
            } else if (j + 1 < NCHUNK) {
                int js = (j + 1) % NSTAGE;
                MBAR_WAIT(base + 8 * js, ((j + 1) / NSTAGE) & 1);
                LOADF(nb, stg + (uint32_t)js * SLOT_B, 0);
            }

            #pragma unroll
            for (int mf = 0; mf < 4; mf++)
                #pragma unroll
                for (int nf = 0; nf < 4; nf++)
                    mma16816(acc[mf][nf], afr[buf][mf], bfr[buf][nf]);
        }

        // Recycled-slot bookkeeping (reads of slot j finished at ks==2;
        // MMA issue above guarantees those LDSM results landed)
        if (j == 0) {
            if (lane == 0) MBAR_ARRIVE(base + 64);           // empty0
            if (tid == 0) {                                  // re-arm chunk 6
                MBAR_WAIT(base + 64, 0);
                tma_issue(base + 0, stg, stg + OP_B, &tmap, 6 * KC, rowA, rowB);
            }
        } else if (j == 1) {
            if (lane == 0) MBAR_ARRIVE(base + 72);           // empty1
            if (tid == 0) {                                  // re-arm chunk 7
                MBAR_WAIT(base + 72, 0);
                uint32_t s1 = stg + SLOT_B;
                tma_issue(base + 8, s1, s1 + OP_B, &tmap, 7 * KC, rowA, rowB);
            }
        }
    }

    // Epilogue: exp(2*dot) + masked sums directly from register fragments.
    const bool diag = (bi == bj);
    const int  dbj  = bj - bi;
    const bool nomt = (dbj == 16) | (dbj == 32) | (dbj == 48);
    const int  grp  = lane >> 2;
    const int  tig  = lane & 3;

    float sum = 0.0f, nom = 0.0f;
    #pragma unroll
    for (int mf = 0; mf < 4; mf++) {
        #pragma unroll
        for (int nf = 0; nf < 4; nf++) {
            int m0 = warp_m * 64 + mf * 16 + grp;
            int n0 = warp_n * 32 + nf * 8 + tig * 2;
            #pragma unroll
            for (int e = 0; e < 4; e++) {
                int mm = m0 + (e >> 1) * 8;
                int nn = n0 + (e & 1);
                float ex = fast_exp2dot(acc[mf][nf][e]);
                if (!diag || nn > mm) sum += ex;
                if (nomt & (nn == mm)) nom += ex;
            }
        }
    }

    // Flat reduction: shfl in-warp, 8 partials in header smem, warp 0 ends.
    #pragma unroll
    for (int o = 16; o > 0; o >>= 1) {
        sum += __shfl_xor_sync(0xFFFFFFFFu, sum, o);
        nom += __shfl_xor_sync(0xFFFFFFFFu, nom, o);
    }
    uint32_t wred = base + 128;   // header region — no stage collision
    if (lane == 0)
        asm volatile("st.shared.v2.f32 [%0], {%1, %2};"
                     :: "r"(wred + 8u * wid), "f"(sum), "f"(nom) : "memory");
    __syncthreads();
    if (wid == 0) {
        float2 v2 = make_float2(0.0f, 0.0f);
        if (lane < 8)
            asm volatile("ld.shared.v2.f32 {%0, %1}, [%2];"
                         : "=f"(v2.x), "=f"(v2.y) : "r"(wred + 8u * lane));
        #pragma unroll
        for (int o = 4; o > 0; o >>= 1) {
            v2.x += __shfl_xor_sync(0xFFFFFFFFu, v2.x, o);
            v2.y += __shfl_xor_sync(0xFFFFFFFFu, v2.y, o);
        }
        if (lane == 0) {
            atomicAdd(&g_acc[0], 2.0 * (double)v2.x);   // mirror lower triangle
            if (v2.y != 0.0f) atomicAdd(&g_acc[1], 2.0 * (double)v2.y);

            // Last-CTA finalize
            __threadfence();
            unsigned int t = atomicAdd(&g_done, 1u);
            if (t == NTILES - 1) {
                __threadfence();
                double nomv = g_acc[1];
                double den  = g_acc[0] - nomv;
                out[0] = (float)(-log(nomv / den) / (double)NROWS);
                g_done = 0;   // reset for next graph replay
            }
        }
    }
    #undef LOADF
}

// ---------------------------------------------------------------------------
// Entry point
// ---------------------------------------------------------------------------
typedef CUresult (*EncodeTiledFn)(
    CUtensorMap*, CUtensorMapDataType, cuuint32_t, void*,
    const cuuint64_t*, const cuuint64_t*, const cuuint32_t*, const cuuint32_t*,
    CUtensorMapInterleave, CUtensorMapSwizzle, CUtensorMapL2promotion,
    CUtensorMapFloatOOBfill);

extern "C" void kernel_launch(void* const* d_in, const int* in_sizes, int n_in,
                              void* d_out, int out_size) {
    const float* emb_i = (const float*)d_in[0];
    const float* emb_j = (const float*)d_in[1];
    float* out = (float*)d_out;

    void* repb_ptr = nullptr;
    cudaGetSymbolAddress(&repb_ptr, g_repb);

    EncodeTiledFn encode = nullptr;
    cudaDriverEntryPointQueryResult qres;
    cudaGetDriverEntryPoint("cuTensorMapEncodeTiled", (void**)&encode,
                            cudaEnableDefault, &qres);

    CUtensorMap tmap;
    cuuint64_t gdim[2]    = {(cuuint64_t)D, (cuuint64_t)NROWS};
    cuuint64_t gstride[1] = {(cuuint64_t)D * 2};            // row pitch bytes
    cuuint32_t box[2]     = {KC, TILE};                     // 64 x 128 elems
    cuuint32_t estride[2] = {1, 1};
    encode(&tmap, CU_TENSOR_MAP_DATA_TYPE_BFLOAT16, 2, repb_ptr,
           gdim, gstride, box, estride,
           CU_TENSOR_MAP_INTERLEAVE_NONE, CU_TENSOR_MAP_SWIZZLE_128B,
           CU_TENSOR_MAP_L2_PROMOTION_L2_128B,
           CU_TENSOR_MAP_FLOAT_OOB_FILL_NONE);

    cudaFuncSetAttribute(gemm_exp_kernel,
                         cudaFuncAttributeMaxDynamicSharedMemorySize, SMEM_DYN);

    normalize_kernel<<<NROWS, 128>>>(emb_i, emb_j);
    gemm_exp_kernel<<<NTILES, NT, SMEM_DYN>>>(out, tmap);
}

// round 10
// speedup vs baseline: 1.3214x; 1.3214x over previous
#include <cuda_runtime.h>
#include <cuda.h>
#include <cuda_bf16.h>
#include <math.h>
#include <cstdint>

// ---------------------------------------------------------------------------
// Problem constants
// ---------------------------------------------------------------------------
#define NROWS 8192       // 4B rows in rep
#define HALF  4096       // rows per input
#define D     512        // embedding dim

// GEMM config: 128x128 CTA tile, 8 warps of 64x32, K chunked by 64 bf16
#define TILE    128
#define KC      64
#define NCHUNK  (D / KC)           // 8
#define NT      256
#define NSTAGE  3
#define OP_B    (TILE * KC * 2)    // 16384 B per operand per stage
#define SLOT_B  (2 * OP_B)         // A + B per stage = 32 KB
#define SMEM_DYN (2048 + NSTAGE * SLOT_B)  // hdr/align + 3 stages = 100352 B

#define NTILES  2080               // 64*65/2 upper-triangular 128x128 tiles

// ---------------------------------------------------------------------------
// Static scratch
// ---------------------------------------------------------------------------
__device__ __align__(16) __nv_bfloat16 g_repb[(size_t)NROWS * D];  // 8 MB
__device__ double g_acc[2];        // [0] = S_offdiag (x2), [1] = nominator
__device__ unsigned int g_done;    // CTA arrival counter (self-resetting)

// ---------------------------------------------------------------------------
// Helpers
// ---------------------------------------------------------------------------
__device__ __forceinline__ uint32_t smem_u32(const void* p) {
    uint32_t a;
    asm("{ .reg .u64 t; cvta.to.shared.u64 t, %1; cvt.u32.u64 %0, t; }"
        : "=r"(a) : "l"(p));
    return a;
}

#define MBAR_INIT(addr, cnt) \
    asm volatile("mbarrier.init.shared.b64 [%0], %1;" :: "r"(addr), "r"(cnt) : "memory")

#define MBAR_ARRIVE(addr) \
    asm volatile("mbarrier.arrive.shared.b64 _, [%0];" :: "r"(addr) : "memory")

#define MBAR_WAIT(addr, par) do {                                              \
    uint32_t _m = (addr), _p = (par), _d;                                      \
    asm volatile("{\n\t.reg .pred p;\n\t"                                      \
        "mbarrier.try_wait.parity.acquire.cta.shared::cta.b64 p, [%1], %2;\n\t"\
        "selp.b32 %0, 1, 0, p;\n\t}"                                           \
        : "=r"(_d) : "r"(_m), "r"(_p) : "memory");                             \
    if (!_d) {                                                                 \
        asm volatile("{\n\t.reg .pred P1;\n\t"                                 \
            "W%=:\n\t"                                                         \
            "mbarrier.try_wait.parity.acquire.cta.shared::cta.b64 P1, [%0], %1, 0x989680;\n\t" \
            "@P1 bra.uni DN%=;\n\tbra.uni W%=;\n\tDN%=:\n\t}"                  \
            :: "r"(_m), "r"(_p) : "memory");                                   \
    }                                                                          \
} while (0)

// TMA: arm barrier for 32KB and issue A+B box loads (64 x 128 bf16, SW128)
__device__ __forceinline__ void tma_issue(uint32_t bar, uint32_t dstA, uint32_t dstB,
                                          const CUtensorMap* tm,
                                          int kx, int rowA, int rowB) {
    asm volatile("mbarrier.arrive.expect_tx.shared.b64 _, [%0], %1;"
                 :: "r"(bar), "r"(32768u) : "memory");
    asm volatile("cp.async.bulk.tensor.2d.shared::cta.global.tile.mbarrier::complete_tx::bytes "
                 "[%0], [%1, {%2, %3}], [%4];"
                 :: "r"(dstA), "l"(tm), "r"(kx), "r"(rowA), "r"(bar) : "memory");
    asm volatile("cp.async.bulk.tensor.2d.shared::cta.global.tile.mbarrier::complete_tx::bytes "
                 "[%0], [%1, {%2, %3}], [%4];"
                 :: "r"(dstB), "l"(tm), "r"(kx), "r"(rowB), "r"(bar) : "memory");
}

__device__ __forceinline__ void ldmx4(uint32_t& r0, uint32_t& r1,
                                      uint32_t& r2, uint32_t& r3, uint32_t a) {
    asm volatile("ldmatrix.sync.aligned.m8n8.x4.shared.b16 {%0,%1,%2,%3}, [%4];"
                 : "=r"(r0), "=r"(r1), "=r"(r2), "=r"(r3) : "r"(a));
}

__device__ __forceinline__ void mma16816(float* c, const uint32_t* a,
                                         const uint32_t* b) {
    asm volatile(
        "mma.sync.aligned.m16n8k16.row.col.f32.bf16.bf16.f32 "
        "{%0,%1,%2,%3}, {%4,%5,%6,%7}, {%8,%9}, {%0,%1,%2,%3};"
        : "+f"(c[0]), "+f"(c[1]), "+f"(c[2]), "+f"(c[3])
        : "r"(a[0]), "r"(a[1]), "r"(a[2]), "r"(a[3]), "r"(b[0]), "r"(b[1]));
}

// FMA-only exp(2*x) via 2^(x*2*log2e). Avoids MUFU. Rel err <= ~4e-6.
__device__ __forceinline__ float fast_exp2dot(float x) {
    float t  = x * 2.88539008177792681f;   // 2*log2(e)
    float fn = t + 12582912.0f;
    int   m  = __float_as_int(fn) - 0x4B400000;
    float r  = t - (fn - 12582912.0f);
    float p  = 1.3333558146e-3f;
    p = fmaf(p, r, 9.6181291e-3f);
    p = fmaf(p, r, 5.5504108664e-2f);
    p = fmaf(p, r, 2.4022650696e-1f);
    p = fmaf(p, r, 6.9314718056e-1f);
    p = fmaf(p, r, 1.0f);
    return __int_as_float(__float_as_int(p) + (m << 23));
}

// ---------------------------------------------------------------------------
// K1: L2-normalize rows of [emb_i; emb_j] -> bf16 g_repb. One block per row.
// Block 0 also zeroes the accumulators.
// ---------------------------------------------------------------------------
__global__ void normalize_kernel(const float* __restrict__ a,
                                 const float* __restrict__ b) {
    int row = blockIdx.x;
    int tid = threadIdx.x;  // 128
    if (row == 0 && tid == 0) { g_acc[0] = 0.0; g_acc[1] = 0.0; }

    const float* src = (row < HALF) ? (a + (size_t)row * D)
                                    : (b + (size_t)(row - HALF) * D);

    float4 v = reinterpret_cast<const float4*>(src)[tid];
    float ss = v.x * v.x + v.y * v.y + v.z * v.z + v.w * v.w;

    #pragma unroll
    for (int o = 16; o > 0; o >>= 1)
        ss += __shfl_xor_sync(0xFFFFFFFFu, ss, o);

    __shared__ float ws[4];
    int wid = tid >> 5, lane = tid & 31;
    if (lane == 0) ws[wid] = ss;
    __syncthreads();

    float total = ws[0] + ws[1] + ws[2] + ws[3];
    float inv = rsqrtf(fmaxf(total, 1e-24f));  // == x / max(norm, 1e-12)

    __nv_bfloat162 lo = __floats2bfloat162_rn(v.x * inv, v.y * inv);
    __nv_bfloat162 hi = __floats2bfloat162_rn(v.z * inv, v.w * inv);
    uint2 pk;
    pk.x = *reinterpret_cast<uint32_t*>(&lo);
    pk.y = *reinterpret_cast<uint32_t*>(&hi);
    reinterpret_cast<uint2*>(g_repb + (size_t)row * D)[tid] = pk;
}

// ---------------------------------------------------------------------------
// K2: bf16 mma.sync GEMM over 2080 upper-triangular tiles. TMA 3-stage ring
// with BARRIER-FREE mainloop: per-slot empty mbarriers (count 8) instead of
// __syncthreads, re-arm of chunk c delegated to warp c-3. Warps free-run
// with up to ~2 chunks of skew so LDSM bursts de-correlate.
// ---------------------------------------------------------------------------
__global__ __launch_bounds__(NT, 2)
void gemm_exp_kernel(float* __restrict__ out,
                     const __grid_constant__ CUtensorMap tmap) {
    // Decode linear tile index -> (bi, bj), bj >= bi.
    int idx = blockIdx.x;
    int bi  = (int)((129.0f - sqrtf(16641.0f - 8.0f * (float)idx)) * 0.5f);
    if (bi > 63) bi = 63;
    while (bi * (129 - bi) / 2 > idx) bi--;
    while ((bi + 1) * (129 - (bi + 1)) / 2 <= idx) bi++;
    int bj = bi + (idx - bi * (129 - bi) / 2);

    extern __shared__ char smraw[];
    uint32_t raw  = smem_u32(smraw);
    uint32_t base = (raw + 1023u) & ~1023u;   // 1024-align (SW128 atom span)
    uint32_t stg  = base + 1024;              // stages start here
    // header: full[s] at base+8*s (s<3); empty[s] at base+32+8*s;
    //         wred at base+128 (64B)

    const int tid    = threadIdx.x;
    const int wid    = tid >> 5;
    const int lane   = tid & 31;
    const int warp_m = wid & 1;      // 2 warps down M (64 rows each)
    const int warp_n = wid >> 1;     // 4 warps across N (32 cols each)

    const int rowA = bi * TILE;
    const int rowB = bj * TILE;

    if (tid == 0) {
        #pragma unroll
        for (int s = 0; s < NSTAGE; s++) {
            MBAR_INIT(base + 8 * s, 1);        // full[s]: TMA completion
            MBAR_INIT(base + 32 + 8 * s, 8);   // empty[s]: 8 warp arrivals
        }
    }
    __syncthreads();

    // Prologue: arm chunks 0..2 into slots 0..2
    if (tid == 0) {
        #pragma unroll
        for (int s = 0; s < NSTAGE; s++) {
            uint32_t sl = stg + (uint32_t)s * SLOT_B;
            tma_issue(base + 8 * s, sl, sl + OP_B, &tmap, s * KC, rowA, rowB);
        }
    }

    float acc[4][4][4];   // [mf][nf][frag]
    #pragma unroll
    for (int mf = 0; mf < 4; mf++)
        #pragma unroll
        for (int nf = 0; nf < 4; nf++)
            #pragma unroll
            for (int e = 0; e < 4; e++)
                acc[mf][nf][e] = 0.0f;

    // Per-lane ldmatrix address components (SW128 swizzle-aware)
    const int a_row = lane & 15;
    const int a_hi  = lane >> 4;
    const int a_sw  = a_row & 7;
    const int b_n   = ((lane >> 4) << 3) + (lane & 7);
    const int b_hi  = (lane >> 3) & 1;
    const int b_sw  = b_n & 7;

    #pragma unroll 1
    for (int j = 0; j < NCHUNK; j++) {
        int slot = j % NSTAGE;
        MBAR_WAIT(base + 8 * slot, (j / NSTAGE) & 1);

        uint32_t sA = stg + (uint32_t)slot * SLOT_B;
        uint32_t sB = sA + OP_B;

        #pragma unroll
        for (int ks = 0; ks < 4; ks++) {
            uint32_t afr[4][4];
            #pragma unroll
            for (int mf = 0; mf < 4; mf++) {
                int grow = warp_m * 64 + mf * 16 + a_row;
                uint32_t ca = (uint32_t)((2 * ks + a_hi) ^ a_sw);
                ldmx4(afr[mf][0], afr[mf][1], afr[mf][2], afr[mf][3],
                      sA + grow * 128 + ca * 16);
            }
            uint32_t bfr[4][2];
            #pragma unroll
            for (int np = 0; np < 2; np++) {
                int gn = warp_n * 32 + np * 16 + b_n;
                uint32_t cb = (uint32_t)((2 * ks + b_hi) ^ b_sw);
                uint32_t r0, r1, r2, r3;
                ldmx4(r0, r1, r2, r3, sB + gn * 128 + cb * 16);
                bfr[2 * np][0] = r0;     bfr[2 * np][1] = r1;
                bfr[2 * np + 1][0] = r2; bfr[2 * np + 1][1] = r3;
            }
            #pragma unroll
            for (int mf = 0; mf < 4; mf++)
                #pragma unroll
                for (int nf = 0; nf < 4; nf++)
                    mma16816(acc[mf][nf], afr[mf], bfr[nf]);
        }

        // Slot recycle without __syncthreads: the ks=3 MMAs above have
        // consumed the last LDSM results from this slot (scoreboard-ordered),
        // so it's safe to signal "done reading".
        if (j < NCHUNK - NSTAGE) {
            if (lane == 0) {
                MBAR_ARRIVE(base + 32 + 8 * slot);   // empty[slot]
                if (wid == j) {
                    // Designated producer for chunk j+3: wait for all 8
                    // warps to release this slot, then re-arm it.
                    MBAR_WAIT(base + 32 + 8 * slot, (j / NSTAGE) & 1);
                    tma_issue(base + 8 * slot, sA, sB, &tmap,
                              (j + NSTAGE) * KC, rowA, rowB);
                }
            }
        }
    }

    // Epilogue: exp(2*dot) + masked sums directly from register fragments.
    const bool diag = (bi == bj);
    const int  dbj  = bj - bi;
    const bool nomt = (dbj == 16) | (dbj == 32) | (dbj == 48);
    const int  grp  = lane >> 2;
    const int  tig  = lane & 3;

    float sum = 0.0f, nom = 0.0f;
    #pragma unroll
    for (int mf = 0; mf < 4; mf++) {
        #pragma unroll
        for (int nf = 0; nf < 4; nf++) {
            int m0 = warp_m * 64 + mf * 16 + grp;
            int n0 = warp_n * 32 + nf * 8 + tig * 2;
            #pragma unroll
            for (int e = 0; e < 4; e++) {
                int mm = m0 + (e >> 1) * 8;
                int nn = n0 + (e & 1);
                float ex = fast_exp2dot(acc[mf][nf][e]);
                if (!diag || nn > mm) sum += ex;
                if (nomt & (nn == mm)) nom += ex;
            }
        }
    }

    // Flat reduction: shfl in-warp, 8 partials in header smem, warp 0 ends.
    #pragma unroll
    for (int o = 16; o > 0; o >>= 1) {
        sum += __shfl_xor_sync(0xFFFFFFFFu, sum, o);
        nom += __shfl_xor_sync(0xFFFFFFFFu, nom, o);
    }
    uint32_t wred = base + 128;   // header region — no stage collision
    if (lane == 0)
        asm volatile("st.shared.v2.f32 [%0], {%1, %2};"
                     :: "r"(wred + 8u * wid), "f"(sum), "f"(nom) : "memory");
    __syncthreads();
    if (wid == 0) {
        float2 v2 = make_float2(0.0f, 0.0f);
        if (lane < 8)
            asm volatile("ld.shared.v2.f32 {%0, %1}, [%2];"
                         : "=f"(v2.x), "=f"(v2.y) : "r"(wred + 8u * lane));
        #pragma unroll
        for (int o = 4; o > 0; o >>= 1) {
            v2.x += __shfl_xor_sync(0xFFFFFFFFu, v2.x, o);
            v2.y += __shfl_xor_sync(0xFFFFFFFFu, v2.y, o);
        }
        if (lane == 0) {
            atomicAdd(&g_acc[0], 2.0 * (double)v2.x);   // mirror lower triangle
            if (v2.y != 0.0f) atomicAdd(&g_acc[1], 2.0 * (double)v2.y);

            // Last-CTA finalize
            __threadfence();
            unsigned int t = atomicAdd(&g_done, 1u);
            if (t == NTILES - 1) {
                __threadfence();
                double nomv = g_acc[1];
                double den  = g_acc[0] - nomv;
                out[0] = (float)(-log(nomv / den) / (double)NROWS);
                g_done = 0;   // reset for next graph replay
            }
        }
    }
}

// ---------------------------------------------------------------------------
// Entry point
// ---------------------------------------------------------------------------
typedef CUresult (*EncodeTiledFn)(
    CUtensorMap*, CUtensorMapDataType, cuuint32_t, void*,
    const cuuint64_t*, const cuuint64_t*, const cuuint32_t*, const cuuint32_t*,
    CUtensorMapInterleave, CUtensorMapSwizzle, CUtensorMapL2promotion,
    CUtensorMapFloatOOBfill);

extern "C" void kernel_launch(void* const* d_in, const int* in_sizes, int n_in,
                              void* d_out, int out_size) {
    const float* emb_i = (const float*)d_in[0];
    const float* emb_j = (const float*)d_in[1];
    float* out = (float*)d_out;

    void* repb_ptr = nullptr;
    cudaGetSymbolAddress(&repb_ptr, g_repb);

    EncodeTiledFn encode = nullptr;
    cudaDriverEntryPointQueryResult qres;
    cudaGetDriverEntryPoint("cuTensorMapEncodeTiled", (void**)&encode,
                            cudaEnableDefault, &qres);

    CUtensorMap tmap;
    cuuint64_t gdim[2]    = {(cuuint64_t)D, (cuuint64_t)NROWS};
    cuuint64_t gstride[1] = {(cuuint64_t)D * 2};            // row pitch bytes
    cuuint32_t box[2]     = {KC, TILE};                     // 64 x 128 elems
    cuuint32_t estride[2] = {1, 1};
    encode(&tmap, CU_TENSOR_MAP_DATA_TYPE_BFLOAT16, 2, repb_ptr,
           gdim, gstride, box, estride,
           CU_TENSOR_MAP_INTERLEAVE_NONE, CU_TENSOR_MAP_SWIZZLE_128B,
           CU_TENSOR_MAP_L2_PROMOTION_L2_128B,
           CU_TENSOR_MAP_FLOAT_OOB_FILL_NONE);

    cudaFuncSetAttribute(gemm_exp_kernel,
                         cudaFuncAttributeMaxDynamicSharedMemorySize, SMEM_DYN);

    normalize_kernel<<<NROWS, 128>>>(emb_i, emb_j);
    gemm_exp_kernel<<<NTILES, NT, SMEM_DYN>>>(out, tmap);
}

// round 11
// speedup vs baseline: 1.3254x; 1.0030x over previous
#include <cuda_runtime.h>
#include <cuda.h>
#include <cuda_bf16.h>
#include <math.h>
#include <cstdint>

// ---------------------------------------------------------------------------
// Problem constants
// ---------------------------------------------------------------------------
#define NROWS 8192       // 4B rows in rep
#define HALF  4096       // rows per input
#define D     512        // embedding dim

// GEMM config: 128x128 CTA tile, 8 warps of 64x32, K chunked by 64 bf16
#define TILE    128
#define KC      64
#define NCHUNK  (D / KC)           // 8
#define NT      256
#define NSTAGE  3
#define OP_B    (TILE * KC * 2)    // 16384 B per operand per stage
#define SLOT_B  (2 * OP_B)         // A + B per stage = 32 KB
#define SMEM_DYN (2048 + NSTAGE * SLOT_B)  // hdr/align + 3 stages = 100352 B

#define NTILES  2080               // 64*65/2 upper-triangular 128x128 tiles
#define GRID    296                // persistent CTAs, 2 per SM

// ---------------------------------------------------------------------------
// Static scratch
// ---------------------------------------------------------------------------
__device__ __align__(16) __nv_bfloat16 g_repb[(size_t)NROWS * D];  // 8 MB
__device__ double g_acc[2];        // [0] = S_offdiag (x2), [1] = nominator
__device__ unsigned int g_done;    // CTA arrival counter (self-resetting)

// ---------------------------------------------------------------------------
// Helpers
// ---------------------------------------------------------------------------
__device__ __forceinline__ uint32_t smem_u32(const void* p) {
    uint32_t a;
    asm("{ .reg .u64 t; cvta.to.shared.u64 t, %1; cvt.u32.u64 %0, t; }"
        : "=r"(a) : "l"(p));
    return a;
}

#define MBAR_INIT(addr, cnt) \
    asm volatile("mbarrier.init.shared.b64 [%0], %1;" :: "r"(addr), "r"(cnt) : "memory")

#define MBAR_ARRIVE(addr) \
    asm volatile("mbarrier.arrive.shared.b64 _, [%0];" :: "r"(addr) : "memory")

#define MBAR_WAIT(addr, par) do {                                              \
    uint32_t _m = (addr), _p = (par), _d;                                      \
    asm volatile("{\n\t.reg .pred p;\n\t"                                      \
        "mbarrier.try_wait.parity.acquire.cta.shared::cta.b64 p, [%1], %2;\n\t"\
        "selp.b32 %0, 1, 0, p;\n\t}"                                           \
        : "=r"(_d) : "r"(_m), "r"(_p) : "memory");                             \
    if (!_d) {                                                                 \
        asm volatile("{\n\t.reg .pred P1;\n\t"                                 \
            "W%=:\n\t"                                                         \
            "mbarrier.try_wait.parity.acquire.cta.shared::cta.b64 P1, [%0], %1, 0x989680;\n\t" \
            "@P1 bra.uni DN%=;\n\tbra.uni W%=;\n\tDN%=:\n\t}"                  \
            :: "r"(_m), "r"(_p) : "memory");                                   \
    }                                                                          \
} while (0)

// TMA: arm barrier for 32KB and issue A+B box loads (64 x 128 bf16, SW128)
__device__ __forceinline__ void tma_issue(uint32_t bar, uint32_t dstA, uint32_t dstB,
                                          const CUtensorMap* tm,
                                          int kx, int rowA, int rowB) {
    asm volatile("mbarrier.arrive.expect_tx.shared.b64 _, [%0], %1;"
                 :: "r"(bar), "r"(32768u) : "memory");
    asm volatile("cp.async.bulk.tensor.2d.shared::cta.global.tile.mbarrier::complete_tx::bytes "
                 "[%0], [%1, {%2, %3}], [%4];"
                 :: "r"(dstA), "l"(tm), "r"(kx), "r"(rowA), "r"(bar) : "memory");
    asm volatile("cp.async.bulk.tensor.2d.shared::cta.global.tile.mbarrier::complete_tx::bytes "
                 "[%0], [%1, {%2, %3}], [%4];"
                 :: "r"(dstB), "l"(tm), "r"(kx), "r"(rowB), "r"(bar) : "memory");
}

__device__ __forceinline__ void ldmx4(uint32_t& r0, uint32_t& r1,
                                      uint32_t& r2, uint32_t& r3, uint32_t a) {
    asm volatile("ldmatrix.sync.aligned.m8n8.x4.shared.b16 {%0,%1,%2,%3}, [%4];"
                 : "=r"(r0), "=r"(r1), "=r"(r2), "=r"(r3) : "r"(a));
}

__device__ __forceinline__ void mma16816(float* c, const uint32_t* a,
                                         const uint32_t* b) {
    asm volatile(
        "mma.sync.aligned.m16n8k16.row.col.f32.bf16.bf16.f32 "
        "{%0,%1,%2,%3}, {%4,%5,%6,%7}, {%8,%9}, {%0,%1,%2,%3};"
        : "+f"(c[0]), "+f"(c[1]), "+f"(c[2]), "+f"(c[3])
        : "r"(a[0]), "r"(a[1]), "r"(a[2]), "r"(a[3]), "r"(b[0]), "r"(b[1]));
}

// exp(2x) = 2^(x * 2*log2(e)) via MUFU.EX2 — 2 instructions, idle pipe.
__device__ __forceinline__ float exp2dot_mufu(float x) {
    float y;
    asm("ex2.approx.f32 %0, %1;" : "=f"(y) : "f"(x * 2.88539008177792681f));
    return y;
}

// Decode linear upper-triangular tile index -> (bi, bj), bj >= bi, 64 rows.
__device__ __forceinline__ void decode_tile(int t, int& bi, int& bj) {
    int b = (int)((129.0f - sqrtf(16641.0f - 8.0f * (float)t)) * 0.5f);
    if (b > 63) b = 63;
    while (b * (129 - b) / 2 > t) b--;
    while ((b + 1) * (129 - (b + 1)) / 2 <= t) b++;
    bi = b;
    bj = b + (t - b * (129 - b) / 2);
}

// ---------------------------------------------------------------------------
// K1: L2-normalize rows of [emb_i; emb_j] -> bf16 g_repb. One block per row.
// Block 0 also zeroes the accumulators.
// ---------------------------------------------------------------------------
__global__ void normalize_kernel(const float* __restrict__ a,
                                 const float* __restrict__ b) {
    int row = blockIdx.x;
    int tid = threadIdx.x;  // 128
    if (row == 0 && tid == 0) { g_acc[0] = 0.0; g_acc[1] = 0.0; }

    const float* src = (row < HALF) ? (a + (size_t)row * D)
                                    : (b + (size_t)(row - HALF) * D);

    float4 v = reinterpret_cast<const float4*>(src)[tid];
    float ss = v.x * v.x + v.y * v.y + v.z * v.z + v.w * v.w;

    #pragma unroll
    for (int o = 16; o > 0; o >>= 1)
        ss += __shfl_xor_sync(0xFFFFFFFFu, ss, o);

    __shared__ float ws[4];
    int wid = tid >> 5, lane = tid & 31;
    if (lane == 0) ws[wid] = ss;
    __syncthreads();

    float total = ws[0] + ws[1] + ws[2] + ws[3];
    float inv = rsqrtf(fmaxf(total, 1e-24f));  // == x / max(norm, 1e-12)

    __nv_bfloat162 lo = __floats2bfloat162_rn(v.x * inv, v.y * inv);
    __nv_bfloat162 hi = __floats2bfloat162_rn(v.z * inv, v.w * inv);
    uint2 pk;
    pk.x = *reinterpret_cast<uint32_t*>(&lo);
    pk.y = *reinterpret_cast<uint32_t*>(&hi);
    reinterpret_cast<uint2*>(g_repb + (size_t)row * D)[tid] = pk;
}

// ---------------------------------------------------------------------------
// K2: PERSISTENT bf16 mma.sync GEMM. 296 CTAs each walk tiles bid+296k.
// Continuous 3-slot TMA ring across tile boundaries (pipeline never drains),
// no __syncthreads / atomics per tile: per-thread running sums, single
// reduction + last-CTA finalize at the end.
// ---------------------------------------------------------------------------
__global__ __launch_bounds__(NT, 2)
void gemm_exp_kernel(float* __restrict__ out,
                     const __grid_constant__ CUtensorMap tmap) {
    extern __shared__ char smraw[];
    uint32_t raw  = smem_u32(smraw);
    uint32_t base = (raw + 1023u) & ~1023u;   // 1024-align (SW128 atom span)
    uint32_t stg  = base + 1024;
    // header: full[s]@base+8s, empty[s]@base+32+8s, wred@base+128

    const int tid    = threadIdx.x;
    const int wid    = tid >> 5;
    const int lane   = tid & 31;
    const int warp_m = wid & 1;
    const int warp_n = wid >> 1;
    const int bid    = blockIdx.x;

    const int nt   = (NTILES - bid + GRID - 1) / GRID;   // tiles for this CTA
    const int Ltot = nt * NCHUNK;                        // total chunk stream

    if (tid == 0) {
        #pragma unroll
        for (int s = 0; s < NSTAGE; s++) {
            MBAR_INIT(base + 8 * s, 1);        // full[s]
            MBAR_INIT(base + 32 + 8 * s, 8);   // empty[s]
        }
    }
    __syncthreads();

    // Tile bookkeeping: current + next tile coordinates
    int biC, bjC, biN = 0, bjN = 0;
    decode_tile(bid, biC, bjC);
    if (nt > 1) decode_tile(bid + GRID, biN, bjN);

    // Prologue: arm chunks 0..2 (all within tile 0)
    if (tid == 0) {
        #pragma unroll
        for (int s = 0; s < NSTAGE; s++) {
            uint32_t sl = stg + (uint32_t)s * SLOT_B;
            tma_issue(base + 8 * s, sl, sl + OP_B, &tmap,
                      s * KC, biC * TILE, bjC * TILE);
        }
    }

    // Per-lane ldmatrix address components (SW128 swizzle-aware)
    const int a_row = lane & 15;
    const int a_hi  = lane >> 4;
    const int a_sw  = a_row & 7;
    const int b_n   = ((lane >> 4) << 3) + (lane & 7);
    const int b_hi  = (lane >> 3) & 1;
    const int b_sw  = b_n & 7;
    const int grp   = lane >> 2;
    const int tig   = lane & 3;

    float sumT = 0.0f, nomT = 0.0f;   // per-thread running sums across tiles
    int L = 0;                         // global chunk counter
    int slot = 0, par = 0;             // ring position + phase parity

    #pragma unroll 1
    for (int ti = 0; ti < nt; ti++) {
        float acc[4][4][4];
        #pragma unroll
        for (int mf = 0; mf < 4; mf++)
            #pragma unroll
            for (int nf = 0; nf < 4; nf++)
                #pragma unroll
                for (int e = 0; e < 4; e++)
                    acc[mf][nf][e] = 0.0f;

        #pragma unroll 1
        for (int j = 0; j < NCHUNK; j++) {
            MBAR_WAIT(base + 8 * slot, par);

            uint32_t sA = stg + (uint32_t)slot * SLOT_B;
            uint32_t sB = sA + OP_B;

            #pragma unroll
            for (int ks = 0; ks < 4; ks++) {
                uint32_t afr[4][4];
                #pragma unroll
                for (int mf = 0; mf < 4; mf++) {
                    int grow = warp_m * 64 + mf * 16 + a_row;
                    uint32_t ca = (uint32_t)((2 * ks + a_hi) ^ a_sw);
                    ldmx4(afr[mf][0], afr[mf][1], afr[mf][2], afr[mf][3],
                          sA + grow * 128 + ca * 16);
                }
                uint32_t bfr[4][2];
                #pragma unroll
                for (int np = 0; np < 2; np++) {
                    int gn = warp_n * 32 + np * 16 + b_n;
                    uint32_t cb = (uint32_t)((2 * ks + b_hi) ^ b_sw);
                    uint32_t r0, r1, r2, r3;
                    ldmx4(r0, r1, r2, r3, sB + gn * 128 + cb * 16);
                    bfr[2 * np][0] = r0;     bfr[2 * np][1] = r1;
                    bfr[2 * np + 1][0] = r2; bfr[2 * np + 1][1] = r3;
                }
                #pragma unroll
                for (int mf = 0; mf < 4; mf++)
                    #pragma unroll
                    for (int nf = 0; nf < 4; nf++)
                        mma16816(acc[mf][nf], afr[mf], bfr[nf]);
            }

            // Continuous slot recycle: designated producer (warp L&7) re-arms
            // this slot with chunk L+3 — possibly belonging to the NEXT tile.
            int Ln = L + NSTAGE;
            if (Ln < Ltot && lane == 0) {
                MBAR_ARRIVE(base + 32 + 8 * slot);
                if (wid == (L & 7)) {
                    MBAR_WAIT(base + 32 + 8 * slot, par);
                    int koff = (Ln % NCHUNK) * KC;
                    bool nx  = (Ln / NCHUNK) != ti;
                    int rA   = (nx ? biN : biC) * TILE;
                    int rB   = (nx ? bjN : bjC) * TILE;
                    tma_issue(base + 8 * slot, sA, sB, &tmap, koff, rA, rB);
                }
            }

            L++;
            if (++slot == NSTAGE) { slot = 0; par ^= 1; }
        }

        // Tile epilogue — no sync, no atomics: accumulate into registers.
        const bool diag = (biC == bjC);
        const int  dbj  = bjC - biC;
        const bool nomt = (dbj == 16) | (dbj == 32) | (dbj == 48);
        #pragma unroll
        for (int mf = 0; mf < 4; mf++) {
            #pragma unroll
            for (int nf = 0; nf < 4; nf++) {
                int m0 = warp_m * 64 + mf * 16 + grp;
                int n0 = warp_n * 32 + nf * 8 + tig * 2;
                #pragma unroll
                for (int e = 0; e < 4; e++) {
                    int mm = m0 + (e >> 1) * 8;
                    int nn = n0 + (e & 1);
                    float ex = exp2dot_mufu(acc[mf][nf][e]);
                    if (!diag || nn > mm) sumT += ex;
                    if (nomt & (nn == mm)) nomT += ex;
                }
            }
        }

        // Rotate tile coordinates
        biC = biN; bjC = bjN;
        if (ti + 2 < nt) decode_tile(bid + (ti + 2) * GRID, biN, bjN);
    }

    // Final reduction: shfl in-warp, 8 partials in header smem, warp 0 ends.
    #pragma unroll
    for (int o = 16; o > 0; o >>= 1) {
        sumT += __shfl_xor_sync(0xFFFFFFFFu, sumT, o);
        nomT += __shfl_xor_sync(0xFFFFFFFFu, nomT, o);
    }
    uint32_t wred = base + 128;
    if (lane == 0)
        asm volatile("st.shared.v2.f32 [%0], {%1, %2};"
                     :: "r"(wred + 8u * wid), "f"(sumT), "f"(nomT) : "memory");
    __syncthreads();
    if (wid == 0) {
        float2 v2 = make_float2(0.0f, 0.0f);
        if (lane < 8)
            asm volatile("ld.shared.v2.f32 {%0, %1}, [%2];"
                         : "=f"(v2.x), "=f"(v2.y) : "r"(wred + 8u * lane));
        #pragma unroll
        for (int o = 4; o > 0; o >>= 1) {
            v2.x += __shfl_xor_sync(0xFFFFFFFFu, v2.x, o);
            v2.y += __shfl_xor_sync(0xFFFFFFFFu, v2.y, o);
        }
        if (lane == 0) {
            atomicAdd(&g_acc[0], 2.0 * (double)v2.x);   // mirror lower triangle
            if (v2.y != 0.0f) atomicAdd(&g_acc[1], 2.0 * (double)v2.y);

            // Last-CTA finalize
            __threadfence();
            unsigned int t = atomicAdd(&g_done, 1u);
            if (t == GRID - 1) {
                __threadfence();
                double nomv = g_acc[1];
                double den  = g_acc[0] - nomv;
                out[0] = (float)(-log(nomv / den) / (double)NROWS);
                g_done = 0;   // reset for next graph replay
            }
        }
    }
}

// ---------------------------------------------------------------------------
// Entry point
// ---------------------------------------------------------------------------
typedef CUresult (*EncodeTiledFn)(
    CUtensorMap*, CUtensorMapDataType, cuuint32_t, void*,
    const cuuint64_t*, const cuuint64_t*, const cuuint32_t*, const cuuint32_t*,
    CUtensorMapInterleave, CUtensorMapSwizzle, CUtensorMapL2promotion,
    CUtensorMapFloatOOBfill);

extern "C" void kernel_launch(void* const* d_in, const int* in_sizes, int n_in,
                              void* d_out, int out_size) {
    const float* emb_i = (const float*)d_in[0];
    const float* emb_j = (const float*)d_in[1];
    float* out = (float*)d_out;

    void* repb_ptr = nullptr;
    cudaGetSymbolAddress(&repb_ptr, g_repb);

    EncodeTiledFn encode = nullptr;
    cudaDriverEntryPointQueryResult qres;
    cudaGetDriverEntryPoint("cuTensorMapEncodeTiled", (void**)&encode,
                            cudaEnableDefault, &qres);

    CUtensorMap tmap;
    cuuint64_t gdim[2]    = {(cuuint64_t)D, (cuuint64_t)NROWS};
    cuuint64_t gstride[1] = {(cuuint64_t)D * 2};            // row pitch bytes
    cuuint32_t box[2]     = {KC, TILE};                     // 64 x 128 elems
    cuuint32_t estride[2] = {1, 1};
    encode(&tmap, CU_TENSOR_MAP_DATA_TYPE_BFLOAT16, 2, repb_ptr,
           gdim, gstride, box, estride,
           CU_TENSOR_MAP_INTERLEAVE_NONE, CU_TENSOR_MAP_SWIZZLE_128B,
           CU_TENSOR_MAP_L2_PROMOTION_L2_128B,
           CU_TENSOR_MAP_FLOAT_OOB_FILL_NONE);

    cudaFuncSetAttribute(gemm_exp_kernel,
                         cudaFuncAttributeMaxDynamicSharedMemorySize, SMEM_DYN);

    normalize_kernel<<<NROWS, 128>>>(emb_i, emb_j);
    gemm_exp_kernel<<<GRID, NT, SMEM_DYN>>>(out, tmap);
}